// round 5
// baseline (speedup 1.0000x reference)
#include <cuda_runtime.h>
#include <math.h>

#define BATCH  4
#define BC     32
#define C_     32
#define W_     14
#define HH     16
#define OUT_HW 29
#define NKL    288              // BC*3*3
#define CWW    6272             // C_*14*14
#define POS    196              // 14*14
#define G      2                // nkl group per block
#define NKLG   (NKL / G)        // 144

// sqrt(var) cache: 4 * 6272 * 16 floats = 1.6 MB
__device__ float g_sv[BATCH * CWW * HH];

__global__ void prep_kernel(const float* __restrict__ var,
                            float* __restrict__ out, int out_n4) {
    int idx = blockIdx.x * blockDim.x + threadIdx.x;
    const int sv_n4 = BATCH * CWW * HH / 4;
    if (idx < sv_n4) {
        float4 v = reinterpret_cast<const float4*>(var)[idx];
        float4 s;
        s.x = sqrtf(v.x); s.y = sqrtf(v.y);
        s.z = sqrtf(v.z); s.w = sqrtf(v.w);
        reinterpret_cast<float4*>(g_sv)[idx] = s;
    }
    if (idx < out_n4)
        reinterpret_cast<float4*>(out)[idx] = make_float4(0.f, 0.f, 0.f, 0.f);
}

__device__ __forceinline__ void fma4(float4& a, float s, const float4& b) {
    a.x = fmaf(s, b.x, a.x);
    a.y = fmaf(s, b.y, a.y);
    a.z = fmaf(s, b.z, a.z);
    a.w = fmaf(s, b.w, a.w);
}

// Lane mapping: lane = sl*4 + v. Warp loads 512B contiguous per stream per
// c-iteration (perfect coalescing). Each lane accumulates partials for its v;
// v-contraction done once at the end via 2 butterfly-shuffle rounds.
// G=2 nkl per block; occupancy 3 CTAs/SM (24 warps) for memory-level
// parallelism; c-loop unrolled x4 to keep ~16 LDG.128 in flight per warp.
__global__ __launch_bounds__(256, 3) void conv_caps_kernel(
    const float* __restrict__ poses,   // mu: (b, CWW, 16)
    const float* __restrict__ Wt,      // (nkl, c, u, v)
    const float* __restrict__ noise,   // (b, nkl, CWW, 16)
    float* __restrict__ out)           // (b, BC, 29, 29, 16)
{
    const int nkl0   = blockIdx.x * G;
    const int b      = blockIdx.y;
    const int schunk = blockIdx.z;     // 64 sites per block

    // W transposed to [g][c][v][u] so a lane reads its 4 u-values as one LDS.128
    __shared__ __align__(16) float sWt[G][C_][4][4];
    for (int t = threadIdx.x; t < G * C_ * 16; t += blockDim.x) {
        int g  = t >> 9;
        int r  = t & 511;
        int u  = (r >> 2) & 3;
        int vv = r & 3;
        int c  = r >> 4;
        sWt[g][c][vv][u] = Wt[(nkl0 + g) * (C_ * 16) + r];
    }
    __syncthreads();

    const int lane = threadIdx.x & 31;
    const int warp = threadIdx.x >> 5;
    const int v    = lane & 3;
    const int sl   = lane >> 2;
    const int site = schunk * 64 + warp * 8 + sl;
    const bool active = (site < POS);

    float4 acc[G][4];
#pragma unroll
    for (int g = 0; g < G; g++)
#pragma unroll
        for (int u = 0; u < 4; u++)
            acc[g][u] = make_float4(0.f, 0.f, 0.f, 0.f);

    if (active) {
        const size_t bq = (size_t)b * (CWW * HH / 4);
        const float4* mu4 = reinterpret_cast<const float4*>(poses) + bq;
        const float4* sv4 = reinterpret_cast<const float4*>(g_sv) + bq;
        const float4* nz0 = reinterpret_cast<const float4*>(noise)
                          + (size_t)(b * NKL + nkl0) * (CWW * HH / 4);
        const float4* nz1 = nz0 + (CWW * HH / 4);

        const int sbase = site * 4 + v;
#pragma unroll 4
        for (int c = 0; c < C_; c++) {
            const int fidx = c * (POS * 4) + sbase;
            float4 mm = mu4[fidx];
            float4 ss = sv4[fidx];
            float4 n0 = nz0[fidx];
            float4 n1 = nz1[fidx];

            float4 vt0, vt1;
            vt0.x = fmaf(ss.x, n0.x, mm.x);
            vt0.y = fmaf(ss.y, n0.y, mm.y);
            vt0.z = fmaf(ss.z, n0.z, mm.z);
            vt0.w = fmaf(ss.w, n0.w, mm.w);
            vt1.x = fmaf(ss.x, n1.x, mm.x);
            vt1.y = fmaf(ss.y, n1.y, mm.y);
            vt1.z = fmaf(ss.z, n1.z, mm.z);
            vt1.w = fmaf(ss.w, n1.w, mm.w);

            const float4 w0 = *reinterpret_cast<const float4*>(&sWt[0][c][v][0]);
            const float4 w1 = *reinterpret_cast<const float4*>(&sWt[1][c][v][0]);
            fma4(acc[0][0], w0.x, vt0);
            fma4(acc[0][1], w0.y, vt0);
            fma4(acc[0][2], w0.z, vt0);
            fma4(acc[0][3], w0.w, vt0);
            fma4(acc[1][0], w1.x, vt1);
            fma4(acc[1][1], w1.y, vt1);
            fma4(acc[1][2], w1.z, vt1);
            fma4(acc[1][3], w1.w, vt1);
        }
    }

    // v-contraction across each 4-lane group (all lanes participate; lanes of
    // inactive sites contribute zeros and stay within their own group).
#pragma unroll
    for (int g = 0; g < G; g++)
#pragma unroll
        for (int u = 0; u < 4; u++) {
            float4 a = acc[g][u];
            a.x += __shfl_xor_sync(0xffffffffu, a.x, 1);
            a.y += __shfl_xor_sync(0xffffffffu, a.y, 1);
            a.z += __shfl_xor_sync(0xffffffffu, a.z, 1);
            a.w += __shfl_xor_sync(0xffffffffu, a.w, 1);
            a.x += __shfl_xor_sync(0xffffffffu, a.x, 2);
            a.y += __shfl_xor_sync(0xffffffffu, a.y, 2);
            a.z += __shfl_xor_sync(0xffffffffu, a.z, 2);
            a.w += __shfl_xor_sync(0xffffffffu, a.w, 2);
            acc[g][u] = a;
        }

    if (active) {
        const int j = site / W_;
        const int i = site % W_;
#pragma unroll
        for (int g = 0; g < G; g++) {
            const int nkl = nkl0 + g;
            const int n = nkl / 9;
            const int k = (nkl / 3) % 3;
            const int l = nkl % 3;
            const int r  = 2 * i + k;
            const int cc = 2 * j + l;
            float4 a = (v == 0) ? acc[g][0]
                     : (v == 1) ? acc[g][1]
                     : (v == 2) ? acc[g][2]
                                : acc[g][3];
            float* o = out + ((((size_t)b * BC + n) * OUT_HW + r) * OUT_HW + cc) * HH
                           + v * 4;
            atomicAdd(o + 0, a.x);
            atomicAdd(o + 1, a.y);
            atomicAdd(o + 2, a.z);
            atomicAdd(o + 3, a.w);
        }
    }
}

extern "C" void kernel_launch(void* const* d_in, const int* in_sizes, int n_in,
                              void* d_out, int out_size) {
    const float* poses = (const float*)d_in[0];
    const float* var   = (const float*)d_in[1];
    const float* Wt    = (const float*)d_in[2];
    const float* noise = (const float*)d_in[3];
    float* out = (float*)d_out;

    const int out_n4 = out_size / 4;
    const int pt = 256;
    const int pb = (out_n4 + pt - 1) / pt;
    prep_kernel<<<pb, pt>>>(var, out, out_n4);

    dim3 grid(NKLG, BATCH, 4);   // 144 nkl-groups x 4 batch x 4 site-chunks
    conv_caps_kernel<<<grid, 256>>>(poses, Wt, noise, out);
}

// round 7
// speedup vs baseline: 1.3383x; 1.3383x over previous
#include <cuda_runtime.h>
#include <math.h>
#include <stdint.h>

#define BATCH  4
#define BC     32
#define C_     32
#define W_     14
#define HH     16
#define OUT_HW 29
#define NKL    288              // BC*3*3
#define CWW    6272             // C_*14*14
#define POS    196              // 14*14
#define G      4                // nkl group per block
#define NKLG   (NKL / G)        // 72

#define DSTAGE       4
#define NSTREAM      (G + 2)                      // mu, sv, 4x noise
#define SLOTS        196                          // 49 sites * 4 v
#define STREAM_BYTES (SLOTS * 16)                 // 3136
#define STAGE_BYTES  (NSTREAM * STREAM_BYTES)     // 18816
#define NCHUNK       4                            // 196 sites = 4 * 49
#define TOT_STAGES   (NCHUNK * C_)                // 128
#define SW_BYTES     (G * C_ * 16 * 4)            // 8192
#define SMEM_BYTES   (DSTAGE * STAGE_BYTES + SW_BYTES)  // 83456

// sqrt(var) cache: 4 * 6272 * 16 floats = 1.6 MB
__device__ float g_sv[BATCH * CWW * HH];

__global__ void prep_kernel(const float* __restrict__ var,
                            float* __restrict__ out, int out_n4) {
    int idx = blockIdx.x * blockDim.x + threadIdx.x;
    const int sv_n4 = BATCH * CWW * HH / 4;
    if (idx < sv_n4) {
        float4 v = reinterpret_cast<const float4*>(var)[idx];
        float4 s;
        s.x = sqrtf(v.x); s.y = sqrtf(v.y);
        s.z = sqrtf(v.z); s.w = sqrtf(v.w);
        reinterpret_cast<float4*>(g_sv)[idx] = s;
    }
    if (idx < out_n4)
        reinterpret_cast<float4*>(out)[idx] = make_float4(0.f, 0.f, 0.f, 0.f);
}

__device__ __forceinline__ void cp_async16(uint32_t dst, const float4* src) {
    // "memory" clobber: must not be hoisted above the smem consume-loads of
    // the slot this refill overwrites.
    asm volatile("cp.async.cg.shared.global [%0], [%1], 16;\n"
                 :: "r"(dst), "l"(src) : "memory");
}
__device__ __forceinline__ void cp_commit() {
    asm volatile("cp.async.commit_group;\n" ::: "memory");
}
__device__ __forceinline__ void cp_wait3() {
    asm volatile("cp.async.wait_group 3;\n" ::: "memory");
}

__device__ __forceinline__ void fma4(float4& a, float s, const float4& b) {
    a.x = fmaf(s, b.x, a.x);
    a.y = fmaf(s, b.y, a.y);
    a.z = fmaf(s, b.z, a.z);
    a.w = fmaf(s, b.w, a.w);
}

// Per-thread cp.async pipeline: thread tid owns slot (site = chunk*49 + tid/4,
// v = tid%4). Each stage = one (chunk, c): thread async-copies its own 16B
// from each of 6 streams into a 4-deep smem ring (register-free MLP), then
// consumes only its own slots — no block barriers in the mainloop.
// Exactly ONE commit_group per iteration (empty groups at the tail) so
// wait_group 3 always proves stage `it` has landed.
__global__ __launch_bounds__(256, 2) void conv_caps_kernel(
    const float* __restrict__ poses,   // mu: (b, CWW, 16)
    const float* __restrict__ Wt,      // (nkl, c, u, v)
    const float* __restrict__ noise,   // (b, nkl, CWW, 16)
    float* __restrict__ out)           // (b, BC, 29, 29, 16)
{
    extern __shared__ __align__(16) unsigned char smem_raw[];
    float* sW = reinterpret_cast<float*>(smem_raw + DSTAGE * STAGE_BYTES);

    const int nkl0 = blockIdx.x * G;
    const int b    = blockIdx.y;
    const int tid  = threadIdx.x;

    // W transposed to [g][c][v][u] so a lane reads its 4 u-values as one LDS.128
    for (int t = tid; t < G * C_ * 16; t += 256) {
        int g  = t >> 9;
        int r  = t & 511;
        int c  = r >> 4;
        int u  = (r >> 2) & 3;
        int vv = r & 3;
        sW[((g * C_ + c) * 4 + vv) * 4 + u] = Wt[(nkl0 + g) * (C_ * 16) + r];
    }
    __syncthreads();
    if (tid >= SLOTS) return;   // no further block-wide barriers below

    const size_t bq = (size_t)b * (CWW * HH / 4);
    const float4* s0 = reinterpret_cast<const float4*>(poses) + bq;   // mu
    const float4* s1 = reinterpret_cast<const float4*>(g_sv) + bq;    // sqrt(var)
    const float4* s2 = reinterpret_cast<const float4*>(noise)
                     + (size_t)(b * NKL + nkl0) * (CWW * HH / 4);
    const float4* s3 = s2 + (CWW * HH / 4);
    const float4* s4 = s3 + (CWW * HH / 4);
    const float4* s5 = s4 + (CWW * HH / 4);

    const uint32_t sb = (uint32_t)__cvta_generic_to_shared(smem_raw) + tid * 16;

    auto issue = [&](int it) {
        const int chunk = it >> 5;
        const int c     = it & 31;
        const int fidx  = c * (POS * 4) + chunk * SLOTS + tid;
        const uint32_t d = sb + (it & (DSTAGE - 1)) * STAGE_BYTES;
        cp_async16(d + 0 * STREAM_BYTES, s0 + fidx);
        cp_async16(d + 1 * STREAM_BYTES, s1 + fidx);
        cp_async16(d + 2 * STREAM_BYTES, s2 + fidx);
        cp_async16(d + 3 * STREAM_BYTES, s3 + fidx);
        cp_async16(d + 4 * STREAM_BYTES, s4 + fidx);
        cp_async16(d + 5 * STREAM_BYTES, s5 + fidx);
        cp_commit();
    };

#pragma unroll
    for (int p = 0; p < DSTAGE; p++) issue(p);

    const int v = tid & 3;
    const unsigned shfl_mask = (tid < 192) ? 0xffffffffu : 0x0000000Fu;

#pragma unroll 1
    for (int chunk = 0; chunk < NCHUNK; chunk++) {
        float4 acc[G][4];
#pragma unroll
        for (int g = 0; g < G; g++)
#pragma unroll
            for (int u = 0; u < 4; u++)
                acc[g][u] = make_float4(0.f, 0.f, 0.f, 0.f);

#pragma unroll 1
        for (int c = 0; c < C_; c++) {
            const int it = chunk * C_ + c;
            cp_wait3();   // one group/iter => stage `it` is complete

            const float4* st = reinterpret_cast<const float4*>(
                smem_raw + (it & (DSTAGE - 1)) * STAGE_BYTES);
            float4 mm = st[0 * SLOTS + tid];
            float4 ss = st[1 * SLOTS + tid];
            float4 n0 = st[2 * SLOTS + tid];
            float4 n1 = st[3 * SLOTS + tid];
            float4 n2 = st[4 * SLOTS + tid];
            float4 n3 = st[5 * SLOTS + tid];

            // Refill the slot just consumed; past the end, commit an EMPTY
            // group so the group count still advances exactly once per iter
            // (this was the R6 tail bug: last 3 stages consumed early).
            if (it + DSTAGE < TOT_STAGES) issue(it + DSTAGE);
            else                          cp_commit();

            float4 vt;
            const float4* wv;

            vt.x = fmaf(ss.x, n0.x, mm.x);
            vt.y = fmaf(ss.y, n0.y, mm.y);
            vt.z = fmaf(ss.z, n0.z, mm.z);
            vt.w = fmaf(ss.w, n0.w, mm.w);
            wv = reinterpret_cast<const float4*>(&sW[((0 * C_ + c) * 4 + v) * 4]);
            fma4(acc[0][0], wv->x, vt);
            fma4(acc[0][1], wv->y, vt);
            fma4(acc[0][2], wv->z, vt);
            fma4(acc[0][3], wv->w, vt);

            vt.x = fmaf(ss.x, n1.x, mm.x);
            vt.y = fmaf(ss.y, n1.y, mm.y);
            vt.z = fmaf(ss.z, n1.z, mm.z);
            vt.w = fmaf(ss.w, n1.w, mm.w);
            wv = reinterpret_cast<const float4*>(&sW[((1 * C_ + c) * 4 + v) * 4]);
            fma4(acc[1][0], wv->x, vt);
            fma4(acc[1][1], wv->y, vt);
            fma4(acc[1][2], wv->z, vt);
            fma4(acc[1][3], wv->w, vt);

            vt.x = fmaf(ss.x, n2.x, mm.x);
            vt.y = fmaf(ss.y, n2.y, mm.y);
            vt.z = fmaf(ss.z, n2.z, mm.z);
            vt.w = fmaf(ss.w, n2.w, mm.w);
            wv = reinterpret_cast<const float4*>(&sW[((2 * C_ + c) * 4 + v) * 4]);
            fma4(acc[2][0], wv->x, vt);
            fma4(acc[2][1], wv->y, vt);
            fma4(acc[2][2], wv->z, vt);
            fma4(acc[2][3], wv->w, vt);

            vt.x = fmaf(ss.x, n3.x, mm.x);
            vt.y = fmaf(ss.y, n3.y, mm.y);
            vt.z = fmaf(ss.z, n3.z, mm.z);
            vt.w = fmaf(ss.w, n3.w, mm.w);
            wv = reinterpret_cast<const float4*>(&sW[((3 * C_ + c) * 4 + v) * 4]);
            fma4(acc[3][0], wv->x, vt);
            fma4(acc[3][1], wv->y, vt);
            fma4(acc[3][2], wv->z, vt);
            fma4(acc[3][3], wv->w, vt);
        }

        // v-contraction across each 4-lane (site) group: 2 butterfly rounds.
        // Warp 6 has only lanes 0-3 alive (tids 192-195) -> mask 0xF.
#pragma unroll
        for (int g = 0; g < G; g++)
#pragma unroll
            for (int u = 0; u < 4; u++) {
                float4 a = acc[g][u];
                a.x += __shfl_xor_sync(shfl_mask, a.x, 1);
                a.y += __shfl_xor_sync(shfl_mask, a.y, 1);
                a.z += __shfl_xor_sync(shfl_mask, a.z, 1);
                a.w += __shfl_xor_sync(shfl_mask, a.w, 1);
                a.x += __shfl_xor_sync(shfl_mask, a.x, 2);
                a.y += __shfl_xor_sync(shfl_mask, a.y, 2);
                a.z += __shfl_xor_sync(shfl_mask, a.z, 2);
                a.w += __shfl_xor_sync(shfl_mask, a.w, 2);
                acc[g][u] = a;
            }

        const int site = chunk * 49 + (tid >> 2);
        const int j = site / W_;
        const int i = site % W_;
#pragma unroll
        for (int g = 0; g < G; g++) {
            const int nkl = nkl0 + g;
            const int n = nkl / 9;
            const int k = (nkl / 3) % 3;
            const int l = nkl % 3;
            const int r  = 2 * i + k;
            const int cc = 2 * j + l;
            // lane v scatters the u==v float4 (group covers all 16 values)
            float4 a = (v == 0) ? acc[g][0]
                     : (v == 1) ? acc[g][1]
                     : (v == 2) ? acc[g][2]
                                : acc[g][3];
            float* o = out + ((((size_t)b * BC + n) * OUT_HW + r) * OUT_HW + cc) * HH
                           + v * 4;
            atomicAdd(o + 0, a.x);
            atomicAdd(o + 1, a.y);
            atomicAdd(o + 2, a.z);
            atomicAdd(o + 3, a.w);
        }
    }
}

extern "C" void kernel_launch(void* const* d_in, const int* in_sizes, int n_in,
                              void* d_out, int out_size) {
    const float* poses = (const float*)d_in[0];
    const float* var   = (const float*)d_in[1];
    const float* Wt    = (const float*)d_in[2];
    const float* noise = (const float*)d_in[3];
    float* out = (float*)d_out;

    // Allow >48KB dynamic smem (idempotent attribute set; capture-safe).
    cudaFuncSetAttribute(conv_caps_kernel,
                         cudaFuncAttributeMaxDynamicSharedMemorySize, SMEM_BYTES);

    const int out_n4 = out_size / 4;
    const int pt = 256;
    const int pb = (out_n4 + pt - 1) / pt;
    prep_kernel<<<pb, pt>>>(var, out, out_n4);

    dim3 grid(NKLG, BATCH);   // 72 x 4 = 288 blocks, all resident in one wave
    conv_caps_kernel<<<grid, 256, SMEM_BYTES>>>(poses, Wt, noise, out);
}